// round 1
// baseline (speedup 1.0000x reference)
#include <cuda_runtime.h>

// ---------------- problem constants ----------------
#define Bsz   64
#define Tst   32
#define D0    4096          // input dim / layer0 out dim
#define M1    (Bsz*Tst)     // 2048 GEMM rows (b*32 + t)
#define K1    4096
#define N1O   4096
#define K2    1024
#define N2O   1000
#define N2P   1024          // padded ld for layer2 delta

// ---------------- scratch (device globals; no allocation) ----------------
__device__ float g_A0[M1 * K1];   // 32 MB  spike matrix layer0 (gathered by idx0)
__device__ float g_D0[M1 * N1O];  // 32 MB  membrane increments layer0
__device__ int   g_N0[Bsz * D0];  // spike counts N = round(x*32)
__device__ int   g_cnt0[Bsz * N1O]; // layer0 fire counts
__device__ int   g_N1[Bsz * K2];    // layer1 encoded N
__device__ float g_A1[M1 * K2];   // 8 MB  spike matrix layer2 input (gathered by idx2)
__device__ float g_D1[M1 * N2P];  // 8 MB  membrane increments layer2

// ---------------- spike evaluation (bit-exact port of to_uniform_spikes) -----
// For 0 < N < T:  spacing = T/N (fp32);  spike(t) = floor(fmod(t, spacing)) == 0
// (the floor(t/spacing) < N condition is provably always true for t < T)
__device__ __forceinline__ float spike_val(int N, int t) {
    if (N <= 0)   return 0.0f;
    if (N >= Tst) return 1.0f;
    float spacing = (float)Tst / (float)N;   // IEEE fp32 divide
    float m = fmodf((float)t, spacing);      // exact
    return (m < 1.0f) ? 1.0f : 0.0f;         // floor(m)==0
}

// ---------------- kernels ----------------
__global__ void k_rates_to_N(const float* __restrict__ x) {
    int i = blockIdx.x * blockDim.x + threadIdx.x;
    if (i < Bsz * D0) g_N0[i] = (int)rintf(x[i] * (float)Tst);  // round half-even
}

__global__ void k_build_A0(const int* __restrict__ idx0) {
    int i = blockIdx.x * blockDim.x + threadIdx.x;
    if (i >= M1 * K1) return;
    int r = i >> 12, j = i & 4095;
    int b = r >> 5,  t = r & 31;
    int d = idx0[j];
    g_A0[i] = spike_val(g_N0[b * D0 + d], t);
}

// C[m, n] = sum_k A[m*K+k] * Bw[n*K+k]   (A: MxK row-major, Bw: NxK row-major)
// BM=BN=128, BK=8, 256 threads, 8x8 per thread. M, K multiples of 128/8; N may be ragged.
__device__ __forceinline__ void gemm_body(const float* __restrict__ A,
                                          const float* __restrict__ Bw,
                                          float* __restrict__ C,
                                          int Nn, int K, int ldc) {
    __shared__ float As[8][128];
    __shared__ float Bs[8][128];
    int tid = threadIdx.x;
    int bm = blockIdx.y * 128, bn = blockIdx.x * 128;
    int lr = tid >> 1;            // 0..127 tile row for loading
    int lc = (tid & 1) * 4;       // 0 or 4 within BK
    int tm = (tid >> 4) * 8;      // 0..120
    int tn = (tid & 15) * 8;      // 0..120

    float acc[8][8];
#pragma unroll
    for (int i = 0; i < 8; i++)
#pragma unroll
        for (int j = 0; j < 8; j++) acc[i][j] = 0.0f;

    for (int k0 = 0; k0 < K; k0 += 8) {
        float4 av = *reinterpret_cast<const float4*>(&A[(size_t)(bm + lr) * K + k0 + lc]);
        int brow = bn + lr;
        float4 bv = make_float4(0.f, 0.f, 0.f, 0.f);
        if (brow < Nn)
            bv = *reinterpret_cast<const float4*>(&Bw[(size_t)brow * K + k0 + lc]);
        __syncthreads();
        As[lc + 0][lr] = av.x; As[lc + 1][lr] = av.y;
        As[lc + 2][lr] = av.z; As[lc + 3][lr] = av.w;
        Bs[lc + 0][lr] = bv.x; Bs[lc + 1][lr] = bv.y;
        Bs[lc + 2][lr] = bv.z; Bs[lc + 3][lr] = bv.w;
        __syncthreads();
#pragma unroll
        for (int kk = 0; kk < 8; kk++) {
            float ar[8], br[8];
#pragma unroll
            for (int i = 0; i < 8; i++) { ar[i] = As[kk][tm + i]; br[i] = Bs[kk][tn + i]; }
#pragma unroll
            for (int i = 0; i < 8; i++)
#pragma unroll
                for (int j = 0; j < 8; j++) acc[i][j] += ar[i] * br[j];
        }
    }
#pragma unroll
    for (int i = 0; i < 8; i++) {
        int row = bm + tm + i;
#pragma unroll
        for (int j = 0; j < 8; j++) {
            int col = bn + tn + j;
            if (col < Nn) C[(size_t)row * ldc + col] = acc[i][j];
        }
    }
}

__global__ void k_gemm1(const float* __restrict__ w0) {
    gemm_body(g_A0, w0, g_D0, N1O, K1, N1O);
}
__global__ void k_gemm2(const float* __restrict__ w2) {
    gemm_body(g_A1, w2, g_D1, N2O, K2, N2P);
}

// LIF scan layer0: count fires per (b, o)
__global__ void k_scan0(const float* __restrict__ t0p) {
    int i = blockIdx.x * blockDim.x + threadIdx.x;
    if (i >= Bsz * N1O) return;
    int b = i >> 12, o = i & 4095;
    float th = *t0p;
    float memb = 0.0f; int cnt = 0;
    const float* col = &g_D0[(size_t)(b * Tst) * N1O + o];
#pragma unroll
    for (int t = 0; t < Tst; t++) {
        memb += col[(size_t)t * N1O];
        if (th < memb) { cnt++; memb -= th; }
    }
    g_cnt0[i] = cnt;
}

// gather idx1 -> rates -> 2x2 avg pool -> clip -> N1 (all arithmetic exact in fp32)
__global__ void k_pool(const int* __restrict__ idx1) {
    int i = blockIdx.x * blockDim.x + threadIdx.x;
    if (i >= Bsz * K2) return;
    int b = i >> 10, m = i & 1023;
    int c = m >> 4, rem = m & 15, pi = rem >> 2, pj = rem & 3;
    int sum = 0;
#pragma unroll
    for (int di = 0; di < 2; di++)
#pragma unroll
        for (int dj = 0; dj < 2; dj++) {
            int h = pi * 2 + di, w = pj * 2 + dj;
            int k = c * 64 + h * 8 + w;
            sum += g_cnt0[b * 4096 + idx1[k]];
        }
    float y = (float)sum * (1.0f / 128.0f);   // (sum/32)/4, exact
    y = fminf(fmaxf(y, 0.0f), 1.0f);
    g_N1[i] = (int)rintf(y * (float)Tst);     // quarter-integers; half-even matches jnp.round
}

__global__ void k_build_A1(const int* __restrict__ idx2) {
    int i = blockIdx.x * blockDim.x + threadIdx.x;
    if (i >= M1 * K2) return;
    int r = i >> 10, k = i & 1023;
    int b = r >> 5,  t = r & 31;
    g_A1[i] = spike_val(g_N1[b * K2 + idx2[k]], t);
}

// LIF scan layer2 + idx_out gather + write output counts
__global__ void k_scan2(const float* __restrict__ t2p, const int* __restrict__ idx_out,
                        float* __restrict__ out) {
    int i = blockIdx.x * blockDim.x + threadIdx.x;
    if (i >= Bsz * N2O) return;
    int b = i / N2O, o = i - b * N2O;
    int col = idx_out[o];
    float th = *t2p;
    float memb = 0.0f; int cnt = 0;
    const float* p = &g_D1[(size_t)(b * Tst) * N2P + col];
#pragma unroll
    for (int t = 0; t < Tst; t++) {
        memb += p[(size_t)t * N2P];
        if (th < memb) { cnt++; memb -= th; }
    }
    out[i] = (float)cnt;
}

// ---------------- launch ----------------
extern "C" void kernel_launch(void* const* d_in, const int* in_sizes, int n_in,
                              void* d_out, int out_size) {
    const float* x    = (const float*)d_in[0];
    const float* w0   = (const float*)d_in[1];
    const float* t0   = (const float*)d_in[2];
    const float* w2   = (const float*)d_in[3];
    const float* t2   = (const float*)d_in[4];
    const int*   idx0 = (const int*)d_in[5];
    const int*   idx1 = (const int*)d_in[6];
    const int*   idx2 = (const int*)d_in[7];
    const int*   idxo = (const int*)d_in[8];
    float* out = (float*)d_out;

    k_rates_to_N<<<(Bsz * D0 + 255) / 256, 256>>>(x);
    k_build_A0<<<(M1 * K1 + 255) / 256, 256>>>(idx0);

    dim3 g1(N1O / 128, M1 / 128);          // (32, 16)
    k_gemm1<<<g1, 256>>>(w0);

    k_scan0<<<(Bsz * N1O + 255) / 256, 256>>>(t0);
    k_pool<<<(Bsz * K2 + 255) / 256, 256>>>(idx1);
    k_build_A1<<<(M1 * K2 + 255) / 256, 256>>>(idx2);

    dim3 g2((N2O + 127) / 128, M1 / 128);  // (8, 16)
    k_gemm2<<<g2, 256>>>(w2);

    k_scan2<<<(Bsz * N2O + 255) / 256, 256>>>(t2, idxo, out);
    (void)in_sizes; (void)n_in; (void)out_size;
}

// round 5
// speedup vs baseline: 3.1208x; 3.1208x over previous
#include <cuda_runtime.h>
#include <cuda_fp16.h>
#include <cstdint>

// ---------------- problem constants ----------------
#define Bsz   64
#define Tst   32
#define M1    2048        // Bsz*Tst GEMM rows
#define K1    4096
#define N1    4096
#define K2    1024
#define N2P   1024        // padded layer2 out
#define N2O   1000

#define LO_SCALE    2048.0f
#define LO_INV      (1.0f / 2048.0f)

// ---------------- scratch (device globals; no allocation) ----------------
__device__ __half g_A0h[M1 * K1];    // spikes layer0 (gathered by idx0), {0,1}
__device__ __half g_W0h[N1 * K1];    // w0 hi split
__device__ __half g_W0l[N1 * K1];    // w0 residual * 2048 (normal-range fp16)
__device__ float  g_D0 [M1 * N1];    // membrane increments layer0
__device__ int    g_N0 [Bsz * K1];
__device__ int    g_cnt0[Bsz * N1];
__device__ int    g_N1 [Bsz * K2];
__device__ __half g_A1h[M1 * K2];
__device__ __half g_W2h[N2P * K2];   // padded, rows >= 1000 zero
__device__ __half g_W2l[N2P * K2];
__device__ float  g_D1 [M1 * N2P];

// ---------------- PTX helpers (baseline ISA only) ----------------
__device__ __forceinline__ uint32_t smem_u32(const void* p) {
    uint32_t a;
    asm("{ .reg .u64 t; cvta.to.shared.u64 t, %1; cvt.u32.u64 %0, t; }" : "=r"(a) : "l"(p));
    return a;
}
#define CP_ASYNC16(dst, src) \
    asm volatile("cp.async.cg.shared.global [%0], [%1], 16;" :: "r"(dst), "l"(src))
#define CP_COMMIT() asm volatile("cp.async.commit_group;" ::: "memory")
#define CP_WAIT2()  asm volatile("cp.async.wait_group 2;" ::: "memory")

#define LDSM4(r0, r1, r2, r3, addr) \
    asm volatile("ldmatrix.sync.aligned.m8n8.x4.shared.b16 {%0,%1,%2,%3}, [%4];" \
                 : "=r"(r0), "=r"(r1), "=r"(r2), "=r"(r3) : "r"(addr))

#define MMA16816(c, a, b) \
    asm volatile("mma.sync.aligned.m16n8k16.row.col.f32.f16.f16.f32 " \
                 "{%0,%1,%2,%3},{%4,%5,%6,%7},{%8,%9},{%0,%1,%2,%3};" \
                 : "+f"((c)[0]), "+f"((c)[1]), "+f"((c)[2]), "+f"((c)[3]) \
                 : "r"((a)[0]), "r"((a)[1]), "r"((a)[2]), "r"((a)[3]), \
                   "r"((b)[0]), "r"((b)[1]))

// ---------------- HMMA GEMM:  C[M x ldc] (+)= scale * A(MxK) @ W^T, fp32 acc ---
// BM=128, BN=128, BK=32, 4-stage cp.async pipeline, 8 warps (2m x 4n), warp 64x32.
#define BKh   32
#define RS    40                   // halves per smem row slot (80 B, conflict-free)
#define STAGE_B (128 * RS * 2 * 2) // A slab + B slab per stage = 20480 B
#define GSMEM  (4 * STAGE_B)       // 81920 B

__global__ void __launch_bounds__(256, 2) gemm_hmma(
    const __half* __restrict__ A, const __half* __restrict__ W,
    float* __restrict__ C, int K, int ldc, float scale, int addmode) {
    extern __shared__ char smem[];
    const uint32_t sb = smem_u32(smem);
    const int tid = threadIdx.x, lane = tid & 31, wid = tid >> 5;
    const int bm = blockIdx.y * 128, bn = blockIdx.x * 128;
    const int warp_m = (wid >> 2) * 64;   // 0 or 64
    const int warp_n = (wid & 3) * 32;    // 0,32,64,96

    const int nkb = K / BKh;

    auto issue = [&](int kb, int stage) {
        int kk = kb * BKh;
        uint32_t sA = sb + stage * STAGE_B;
        uint32_t sB = sA + 128 * RS * 2;
#pragma unroll
        for (int i = tid; i < 1024; i += 256) {
            int isB = (i >> 9);
            int t = i & 511;
            int row = t >> 2, kc = (t & 3) * 8;
            uint32_t dst = (isB ? sB : sA) + (uint32_t)(row * RS + kc) * 2;
            const __half* src = isB ? (W + (size_t)(bn + row) * K + kk + kc)
                                    : (A + (size_t)(bm + row) * K + kk + kc);
            CP_ASYNC16(dst, src);
        }
        CP_COMMIT();
    };

    float cc[4][4][4];
#pragma unroll
    for (int i = 0; i < 4; i++)
#pragma unroll
        for (int j = 0; j < 4; j++)
#pragma unroll
            for (int q = 0; q < 4; q++) cc[i][j][q] = 0.0f;

    issue(0, 0); issue(1, 1); issue(2, 2);

    const int a_r = (lane & 15), a_c8 = ((lane >> 4) << 3);
    const int b_r = ((lane >> 4) << 3) + (lane & 7), b_c8 = ((lane >> 3) & 1) << 3;

    for (int kb = 0; kb < nkb; kb++) {
        CP_WAIT2();
        __syncthreads();
        if (kb + 3 < nkb) issue(kb + 3, (kb + 3) & 3);

        uint32_t sA = sb + (kb & 3) * STAGE_B;
        uint32_t sB = sA + 128 * RS * 2;
#pragma unroll
        for (int ks = 0; ks < 32; ks += 16) {
            uint32_t a[4][4], b[4][2];
#pragma unroll
            for (int mf = 0; mf < 4; mf++) {
                uint32_t ad = sA + (uint32_t)((warp_m + mf * 16 + a_r) * RS + ks + a_c8) * 2;
                LDSM4(a[mf][0], a[mf][1], a[mf][2], a[mf][3], ad);
            }
#pragma unroll
            for (int bg = 0; bg < 2; bg++) {
                uint32_t bd = sB + (uint32_t)((warp_n + bg * 16 + b_r) * RS + ks + b_c8) * 2;
                LDSM4(b[2 * bg][0], b[2 * bg][1], b[2 * bg + 1][0], b[2 * bg + 1][1], bd);
            }
#pragma unroll
            for (int mf = 0; mf < 4; mf++)
#pragma unroll
                for (int nf = 0; nf < 4; nf++)
                    MMA16816(cc[mf][nf], a[mf], b[nf]);
        }
        __syncthreads();
    }

    // epilogue
#pragma unroll
    for (int mf = 0; mf < 4; mf++) {
        int r0 = bm + warp_m + mf * 16 + (lane >> 2);
#pragma unroll
        for (int nf = 0; nf < 4; nf++) {
            int c0 = bn + warp_n + nf * 8 + (lane & 3) * 2;
            float2* p0 = reinterpret_cast<float2*>(&C[(size_t)r0 * ldc + c0]);
            float2* p1 = reinterpret_cast<float2*>(&C[(size_t)(r0 + 8) * ldc + c0]);
            if (addmode) {
                float2 o0 = *p0, o1 = *p1;
                *p0 = make_float2(o0.x + scale * cc[mf][nf][0], o0.y + scale * cc[mf][nf][1]);
                *p1 = make_float2(o1.x + scale * cc[mf][nf][2], o1.y + scale * cc[mf][nf][3]);
            } else {
                *p0 = make_float2(cc[mf][nf][0], cc[mf][nf][1]);
                *p1 = make_float2(cc[mf][nf][2], cc[mf][nf][3]);
            }
        }
    }
}

// ---------------- spike evaluation (bit-exact port) ----------------
__device__ __forceinline__ float spike_val(int N, int t) {
    if (N <= 0)   return 0.0f;
    if (N >= Tst) return 1.0f;
    float spacing = (float)Tst / (float)N;
    float m = fmodf((float)t, spacing);
    return (m < 1.0f) ? 1.0f : 0.0f;
}

// ---------------- small kernels ----------------
__global__ void k_rates_to_N(const float* __restrict__ x) {
    int i = blockIdx.x * blockDim.x + threadIdx.x;
    if (i < Bsz * K1) g_N0[i] = (int)rintf(x[i] * (float)Tst);
}

__global__ void k_split_w0(const float* __restrict__ w) {
    int i = blockIdx.x * blockDim.x + threadIdx.x;
    if (i >= N1 * K1) return;
    float v = w[i];
    __half h = __float2half(v);
    g_W0h[i] = h;
    g_W0l[i] = __float2half((v - __half2float(h)) * LO_SCALE);  // normal-range
}

__global__ void k_split_w2(const float* __restrict__ w) {
    int i = blockIdx.x * blockDim.x + threadIdx.x;
    if (i >= N2P * K2) return;
    int n = i >> 10, k = i & 1023;
    float v = (n < N2O) ? w[n * K2 + k] : 0.0f;
    __half h = __float2half(v);
    g_W2h[i] = h;
    g_W2l[i] = __float2half((v - __half2float(h)) * LO_SCALE);
}

__global__ void k_build_A0(const int* __restrict__ idx0) {
    int i = blockIdx.x * blockDim.x + threadIdx.x;
    if (i >= M1 * K1) return;
    int r = i >> 12, j = i & 4095;
    int b = r >> 5, t = r & 31;
    g_A0h[i] = __float2half(spike_val(g_N0[b * K1 + idx0[j]], t));
}

__global__ void k_scan0(const float* __restrict__ t0p) {
    int i = blockIdx.x * blockDim.x + threadIdx.x;
    if (i >= Bsz * N1) return;
    int b = i >> 12, o = i & 4095;
    float th = *t0p;
    float memb = 0.0f; int cnt = 0;
    const float* col = &g_D0[(size_t)(b * Tst) * N1 + o];
#pragma unroll
    for (int t = 0; t < Tst; t++) {
        memb += col[(size_t)t * N1];
        if (th < memb) { cnt++; memb -= th; }
    }
    g_cnt0[i] = cnt;
}

__global__ void k_pool(const int* __restrict__ idx1) {
    int i = blockIdx.x * blockDim.x + threadIdx.x;
    if (i >= Bsz * K2) return;
    int b = i >> 10, m = i & 1023;
    int c = m >> 4, rem = m & 15, pi = rem >> 2, pj = rem & 3;
    int sum = 0;
#pragma unroll
    for (int di = 0; di < 2; di++)
#pragma unroll
        for (int dj = 0; dj < 2; dj++) {
            int k = c * 64 + (pi * 2 + di) * 8 + (pj * 2 + dj);
            sum += g_cnt0[b * 4096 + idx1[k]];
        }
    float y = (float)sum * (1.0f / 128.0f);
    y = fminf(fmaxf(y, 0.0f), 1.0f);
    g_N1[i] = (int)rintf(y * (float)Tst);
}

__global__ void k_build_A1(const int* __restrict__ idx2) {
    int i = blockIdx.x * blockDim.x + threadIdx.x;
    if (i >= M1 * K2) return;
    int r = i >> 10, k = i & 1023;
    int b = r >> 5, t = r & 31;
    g_A1h[i] = __float2half(spike_val(g_N1[b * K2 + idx2[k]], t));
}

__global__ void k_scan2(const float* __restrict__ t2p, const int* __restrict__ idx_out,
                        float* __restrict__ out) {
    int i = blockIdx.x * blockDim.x + threadIdx.x;
    if (i >= Bsz * N2O) return;
    int b = i / N2O, o = i - b * N2O;
    int col = idx_out[o];
    float th = *t2p;
    float memb = 0.0f; int cnt = 0;
    const float* p = &g_D1[(size_t)(b * Tst) * N2P + col];
#pragma unroll
    for (int t = 0; t < Tst; t++) {
        memb += p[(size_t)t * N2P];
        if (th < memb) { cnt++; memb -= th; }
    }
    out[i] = (float)cnt;
}

// ---------------- launch ----------------
extern "C" void kernel_launch(void* const* d_in, const int* in_sizes, int n_in,
                              void* d_out, int out_size) {
    const float* x    = (const float*)d_in[0];
    const float* w0   = (const float*)d_in[1];
    const float* t0   = (const float*)d_in[2];
    const float* w2   = (const float*)d_in[3];
    const float* t2   = (const float*)d_in[4];
    const int*   idx0 = (const int*)d_in[5];
    const int*   idx1 = (const int*)d_in[6];
    const int*   idx2 = (const int*)d_in[7];
    const int*   idxo = (const int*)d_in[8];
    float* out = (float*)d_out;

    void *pA0, *pW0h, *pW0l, *pD0, *pA1, *pW2h, *pW2l, *pD1;
    cudaGetSymbolAddress(&pA0, g_A0h);
    cudaGetSymbolAddress(&pW0h, g_W0h);
    cudaGetSymbolAddress(&pW0l, g_W0l);
    cudaGetSymbolAddress(&pD0, g_D0);
    cudaGetSymbolAddress(&pA1, g_A1h);
    cudaGetSymbolAddress(&pW2h, g_W2h);
    cudaGetSymbolAddress(&pW2l, g_W2l);
    cudaGetSymbolAddress(&pD1, g_D1);

    cudaFuncSetAttribute(gemm_hmma, cudaFuncAttributeMaxDynamicSharedMemorySize, GSMEM);

    k_rates_to_N<<<(Bsz * K1 + 255) / 256, 256>>>(x);
    k_split_w0<<<(N1 * K1 + 255) / 256, 256>>>(w0);
    k_split_w2<<<(N2P * K2 + 255) / 256, 256>>>(w2);
    k_build_A0<<<(M1 * K1 + 255) / 256, 256>>>(idx0);

    dim3 g1(N1 / 128, M1 / 128);
    gemm_hmma<<<g1, 256, GSMEM>>>((const __half*)pA0, (const __half*)pW0h,
                                  (float*)pD0, K1, N1, 1.0f, 0);
    gemm_hmma<<<g1, 256, GSMEM>>>((const __half*)pA0, (const __half*)pW0l,
                                  (float*)pD0, K1, N1, LO_INV, 1);

    k_scan0<<<(Bsz * N1 + 255) / 256, 256>>>(t0);
    k_pool<<<(Bsz * K2 + 255) / 256, 256>>>(idx1);
    k_build_A1<<<(M1 * K2 + 255) / 256, 256>>>(idx2);

    dim3 g2(N2P / 128, M1 / 128);
    gemm_hmma<<<g2, 256, GSMEM>>>((const __half*)pA1, (const __half*)pW2h,
                                  (float*)pD1, K2, N2P, 1.0f, 0);
    gemm_hmma<<<g2, 256, GSMEM>>>((const __half*)pA1, (const __half*)pW2l,
                                  (float*)pD1, K2, N2P, LO_INV, 1);

    k_scan2<<<(Bsz * N2O + 255) / 256, 256>>>(t2, idxo, out);
    (void)in_sizes; (void)n_in; (void)out_size;
}

// round 11
// speedup vs baseline: 3.5933x; 1.1514x over previous
#include <cuda_runtime.h>
#include <cuda_fp16.h>
#include <cstdint>

// ---------------- problem constants ----------------
#define Bsz   64
#define Tst   32
#define M1    2048        // Bsz*Tst GEMM rows
#define K1    4096
#define N1    4096
#define K2    1024
#define N2P   1024
#define N2O   1000

#define LO_SCALE    2048.0f
#define LO_INV      (1.0f / 2048.0f)

// ---------------- scratch (device globals; no allocation) ----------------
__device__ __half    g_A0h[M1 * K1];
__device__ __half    g_W0h[N1 * K1];
__device__ __half    g_W0l[N1 * K1];     // residual * 2048
__device__ float     g_D0 [M1 * N1];     // hi-pass partial for layer0
__device__ uint32_t  g_mask0[Bsz * K1];
__device__ int       g_cnt0[Bsz * N1];
__device__ uint32_t  g_mask1[Bsz * K2];
__device__ __half    g_A1h[M1 * K2];
__device__ __half    g_W2h[N2P * K2];
__device__ __half    g_W2l[N2P * K2];
__device__ float     g_D1 [M1 * N2P];
__device__ int       g_cnt2[Bsz * N2P];

// ---------------- PTX helpers (baseline ISA only) ----------------
__device__ __forceinline__ uint32_t smem_u32(const void* p) {
    uint32_t a;
    asm("{ .reg .u64 t; cvta.to.shared.u64 t, %1; cvt.u32.u64 %0, t; }" : "=r"(a) : "l"(p));
    return a;
}
#define CP_ASYNC16(dst, src) \
    asm volatile("cp.async.cg.shared.global [%0], [%1], 16;" :: "r"(dst), "l"(src))
#define CP_COMMIT() asm volatile("cp.async.commit_group;" ::: "memory")
#define CP_WAIT2()  asm volatile("cp.async.wait_group 2;" ::: "memory")

#define LDSM4(r0, r1, r2, r3, addr) \
    asm volatile("ldmatrix.sync.aligned.m8n8.x4.shared.b16 {%0,%1,%2,%3}, [%4];" \
                 : "=r"(r0), "=r"(r1), "=r"(r2), "=r"(r3) : "r"(addr))

#define MMA16816(c, a, b) \
    asm volatile("mma.sync.aligned.m16n8k16.row.col.f32.f16.f16.f32 " \
                 "{%0,%1,%2,%3},{%4,%5,%6,%7},{%8,%9},{%0,%1,%2,%3};" \
                 : "+f"((c)[0]), "+f"((c)[1]), "+f"((c)[2]), "+f"((c)[3]) \
                 : "r"((a)[0]), "r"((a)[1]), "r"((a)[2]), "r"((a)[3]), \
                   "r"((b)[0]), "r"((b)[1]))

// ---------------- GEMM mainloop (shared by both passes) ----------------
// BM=128, BN=128, BK=32, 4-stage cp.async, 8 warps (2m x 4n), warp 64x32.
// Single barrier per K-block: the top __syncthreads (after wait_group) both
// publishes stage kb to all warps and proves all warps finished stage kb-1
// reads (program order) before anyone overwrites that stage via issue(kb+3).
#define BKh   32
#define RS    40                   // halves per smem row (80 B, ldmatrix conflict-free)
#define STAGE_B (128 * RS * 2 * 2) // 20480 B per stage
#define GSMEM  (4 * STAGE_B)       // 81920 B; also covers 128*132*4 epilogue floats
#define EPITCH 132

__device__ __forceinline__ void gemm_mainloop(
    const __half* __restrict__ A, const __half* __restrict__ W,
    float cc[4][4][4], uint32_t sb, int K, int bm, int bn,
    int tid, int lane, int warp_m, int warp_n) {

    const int nkb = K / BKh;

    auto issue = [&](int kb, int stage) {
        int kk = kb * BKh;
        uint32_t sA = sb + stage * STAGE_B;
        uint32_t sB = sA + 128 * RS * 2;
#pragma unroll
        for (int i = tid; i < 1024; i += 256) {
            int isB = (i >> 9);
            int t = i & 511;
            int row = t >> 2, kc = (t & 3) * 8;
            uint32_t dst = (isB ? sB : sA) + (uint32_t)(row * RS + kc) * 2;
            const __half* src = isB ? (W + (size_t)(bn + row) * K + kk + kc)
                                    : (A + (size_t)(bm + row) * K + kk + kc);
            CP_ASYNC16(dst, src);
        }
        CP_COMMIT();
    };

    issue(0, 0); issue(1, 1); issue(2, 2);

    const int a_r = (lane & 15), a_c8 = ((lane >> 4) << 3);
    const int b_r = ((lane >> 4) << 3) + (lane & 7), b_c8 = ((lane >> 3) & 1) << 3;

    for (int kb = 0; kb < nkb; kb++) {
        CP_WAIT2();
        __syncthreads();
        if (kb + 3 < nkb) issue(kb + 3, (kb + 3) & 3);

        uint32_t sA = sb + (kb & 3) * STAGE_B;
        uint32_t sB = sA + 128 * RS * 2;
#pragma unroll
        for (int ks = 0; ks < 32; ks += 16) {
            uint32_t a[4][4], b[4][2];
#pragma unroll
            for (int mf = 0; mf < 4; mf++) {
                uint32_t ad = sA + (uint32_t)((warp_m + mf * 16 + a_r) * RS + ks + a_c8) * 2;
                LDSM4(a[mf][0], a[mf][1], a[mf][2], a[mf][3], ad);
            }
#pragma unroll
            for (int bg = 0; bg < 2; bg++) {
                uint32_t bd = sB + (uint32_t)((warp_n + bg * 16 + b_r) * RS + ks + b_c8) * 2;
                LDSM4(b[2 * bg][0], b[2 * bg][1], b[2 * bg + 1][0], b[2 * bg + 1][1], bd);
            }
#pragma unroll
            for (int mf = 0; mf < 4; mf++)
#pragma unroll
                for (int nf = 0; nf < 4; nf++)
                    MMA16816(cc[mf][nf], a[mf], b[nf]);
        }
    }
    __syncthreads();   // mainloop smem free after this
}

// ---- pass 1: D = A @ Wh^T (store) ----
__global__ void __launch_bounds__(256, 2) gemm_hi(
    const __half* __restrict__ A, const __half* __restrict__ W,
    float* __restrict__ C, int K, int ldc) {
    extern __shared__ char smem[];
    const uint32_t sb = smem_u32(smem);
    const int tid = threadIdx.x, lane = tid & 31, wid = tid >> 5;
    const int bm = blockIdx.y * 128, bn = blockIdx.x * 128;
    const int warp_m = (wid >> 2) * 64, warp_n = (wid & 3) * 32;

    float cc[4][4][4];
#pragma unroll
    for (int i = 0; i < 4; i++)
#pragma unroll
        for (int j = 0; j < 4; j++)
#pragma unroll
            for (int q = 0; q < 4; q++) cc[i][j][q] = 0.0f;

    gemm_mainloop(A, W, cc, sb, K, bm, bn, tid, lane, warp_m, warp_n);

#pragma unroll
    for (int mf = 0; mf < 4; mf++) {
        int r0 = bm + warp_m + mf * 16 + (lane >> 2);
#pragma unroll
        for (int nf = 0; nf < 4; nf++) {
            int c0 = bn + warp_n + nf * 8 + (lane & 3) * 2;
            *reinterpret_cast<float2*>(&C[(size_t)r0 * ldc + c0]) =
                make_float2(cc[mf][nf][0], cc[mf][nf][1]);
            *reinterpret_cast<float2*>(&C[(size_t)(r0 + 8) * ldc + c0]) =
                make_float2(cc[mf][nf][2], cc[mf][nf][3]);
        }
    }
}

// ---- pass 2: D = Cin + LO_INV * (A @ Wl^T), then LIF scan -> counts ----
// (combine expression identical to round-5 addmode epilogue: o + scale*cc)
__global__ void __launch_bounds__(256, 2) gemm_lo_lif(
    const __half* __restrict__ A, const __half* __restrict__ W,
    const float* __restrict__ Cin, int* __restrict__ cnt,
    const float* __restrict__ thp, int K, int ldc) {
    extern __shared__ char smem[];
    const uint32_t sb = smem_u32(smem);
    const int tid = threadIdx.x, lane = tid & 31, wid = tid >> 5;
    const int bm = blockIdx.y * 128, bn = blockIdx.x * 128;
    const int warp_m = (wid >> 2) * 64, warp_n = (wid & 3) * 32;

    float cc[4][4][4];
#pragma unroll
    for (int i = 0; i < 4; i++)
#pragma unroll
        for (int j = 0; j < 4; j++)
#pragma unroll
            for (int q = 0; q < 4; q++) cc[i][j][q] = 0.0f;

    gemm_mainloop(A, W, cc, sb, K, bm, bn, tid, lane, warp_m, warp_n);

    // stage D = hi + LO_INV*lo into smem (tile-local), then scan
    float* ep = reinterpret_cast<float*>(smem);
#pragma unroll
    for (int mf = 0; mf < 4; mf++) {
        int rl = warp_m + mf * 16 + (lane >> 2);
        int rg = bm + rl;
#pragma unroll
        for (int nf = 0; nf < 4; nf++) {
            int cl = warp_n + nf * 8 + (lane & 3) * 2;
            int cg = bn + cl;
            float2 o0 = *reinterpret_cast<const float2*>(&Cin[(size_t)rg * ldc + cg]);
            float2 o1 = *reinterpret_cast<const float2*>(&Cin[(size_t)(rg + 8) * ldc + cg]);
            ep[rl * EPITCH + cl]           = o0.x + LO_INV * cc[mf][nf][0];
            ep[rl * EPITCH + cl + 1]       = o0.y + LO_INV * cc[mf][nf][1];
            ep[(rl + 8) * EPITCH + cl]     = o1.x + LO_INV * cc[mf][nf][2];
            ep[(rl + 8) * EPITCH + cl + 1] = o1.y + LO_INV * cc[mf][nf][3];
        }
    }
    __syncthreads();
    float th = *thp;
#pragma unroll
    for (int task = tid; task < 512; task += 256) {
        int bb = task >> 7, oo = task & 127;
        const float* col = ep + (bb * 32) * EPITCH + oo;
        float memb = 0.0f; int c = 0;
#pragma unroll
        for (int t = 0; t < Tst; t++) {
            memb += col[t * EPITCH];
            if (th < memb) { c++; memb -= th; }
        }
        cnt[((bm >> 5) + bb) * ldc + bn + oo] = c;
    }
}

// ---------------- spike mask (bit-exact port of to_uniform_spikes) ----------
__device__ __forceinline__ uint32_t spike_mask(int N) {
    if (N <= 0)   return 0u;
    if (N >= Tst) return 0xFFFFFFFFu;
    float sp = (float)Tst / (float)N;
    uint32_t m = 0;
#pragma unroll
    for (int t = 0; t < Tst; t++)
        if (fmodf((float)t, sp) < 1.0f) m |= (1u << t);
    return m;
}

// ---------------- small kernels ----------------
__global__ void k_mask0(const float* __restrict__ x) {
    int i = blockIdx.x * blockDim.x + threadIdx.x;
    if (i < Bsz * K1) g_mask0[i] = spike_mask((int)rintf(x[i] * (float)Tst));
}

__global__ void k_split_w0(const float* __restrict__ w) {
    int i4 = blockIdx.x * blockDim.x + threadIdx.x;
    if (i4 >= (N1 * K1) / 4) return;
    float4 v = reinterpret_cast<const float4*>(w)[i4];
    __half h0 = __float2half(v.x), h1 = __float2half(v.y);
    __half h2 = __float2half(v.z), h3 = __float2half(v.w);
    __half2* ph = reinterpret_cast<__half2*>(g_W0h) + i4 * 2;
    ph[0] = __halves2half2(h0, h1); ph[1] = __halves2half2(h2, h3);
    __half2* pl = reinterpret_cast<__half2*>(g_W0l) + i4 * 2;
    pl[0] = __halves2half2(__float2half((v.x - __half2float(h0)) * LO_SCALE),
                           __float2half((v.y - __half2float(h1)) * LO_SCALE));
    pl[1] = __halves2half2(__float2half((v.z - __half2float(h2)) * LO_SCALE),
                           __float2half((v.w - __half2float(h3)) * LO_SCALE));
}

__global__ void k_split_w2(const float* __restrict__ w) {
    int i = blockIdx.x * blockDim.x + threadIdx.x;
    if (i >= N2P * K2) return;
    int n = i >> 10, k = i & 1023;
    float v = (n < N2O) ? w[n * K2 + k] : 0.0f;
    __half h = __float2half(v);
    g_W2h[i] = h;
    g_W2l[i] = __float2half((v - __half2float(h)) * LO_SCALE);
}

__global__ void k_build_A0(const int* __restrict__ idx0) {
    int i8 = blockIdx.x * blockDim.x + threadIdx.x;
    if (i8 >= (M1 * K1) / 8) return;
    int base = i8 * 8;
    int r = base >> 12, j0 = base & 4095;
    int b = r >> 5, t = r & 31;
    const int4* ip = reinterpret_cast<const int4*>(idx0 + j0);
    int4 iv0 = ip[0], iv1 = ip[1];
    const uint32_t* mk = g_mask0 + b * K1;
    int d[8] = {iv0.x, iv0.y, iv0.z, iv0.w, iv1.x, iv1.y, iv1.z, iv1.w};
    uint16_t h[8];
#pragma unroll
    for (int q = 0; q < 8; q++)
        h[q] = ((mk[d[q]] >> t) & 1u) ? 0x3C00 : 0x0000;
    reinterpret_cast<uint4*>(g_A0h)[i8] =
        make_uint4((uint32_t)h[0] | ((uint32_t)h[1] << 16),
                   (uint32_t)h[2] | ((uint32_t)h[3] << 16),
                   (uint32_t)h[4] | ((uint32_t)h[5] << 16),
                   (uint32_t)h[6] | ((uint32_t)h[7] << 16));
}

__global__ void k_pool(const int* __restrict__ idx1) {
    int i = blockIdx.x * blockDim.x + threadIdx.x;
    if (i >= Bsz * K2) return;
    int b = i >> 10, m = i & 1023;
    int c = m >> 4, rem = m & 15, pi = rem >> 2, pj = rem & 3;
    int sum = 0;
#pragma unroll
    for (int di = 0; di < 2; di++)
#pragma unroll
        for (int dj = 0; dj < 2; dj++) {
            int k = c * 64 + (pi * 2 + di) * 8 + (pj * 2 + dj);
            sum += g_cnt0[b * 4096 + idx1[k]];
        }
    float y = (float)sum * (1.0f / 128.0f);
    y = fminf(fmaxf(y, 0.0f), 1.0f);
    g_mask1[i] = spike_mask((int)rintf(y * (float)Tst));
}

__global__ void k_build_A1(const int* __restrict__ idx2) {
    int i8 = blockIdx.x * blockDim.x + threadIdx.x;
    if (i8 >= (M1 * K2) / 8) return;
    int base = i8 * 8;
    int r = base >> 10, j0 = base & 1023;
    int b = r >> 5, t = r & 31;
    const int4* ip = reinterpret_cast<const int4*>(idx2 + j0);
    int4 iv0 = ip[0], iv1 = ip[1];
    const uint32_t* mk = g_mask1 + b * K2;
    int d[8] = {iv0.x, iv0.y, iv0.z, iv0.w, iv1.x, iv1.y, iv1.z, iv1.w};
    uint16_t h[8];
#pragma unroll
    for (int q = 0; q < 8; q++)
        h[q] = ((mk[d[q]] >> t) & 1u) ? 0x3C00 : 0x0000;
    reinterpret_cast<uint4*>(g_A1h)[i8] =
        make_uint4((uint32_t)h[0] | ((uint32_t)h[1] << 16),
                   (uint32_t)h[2] | ((uint32_t)h[3] << 16),
                   (uint32_t)h[4] | ((uint32_t)h[5] << 16),
                   (uint32_t)h[6] | ((uint32_t)h[7] << 16));
}

__global__ void k_out(const int* __restrict__ idx_out, float* __restrict__ out) {
    int i = blockIdx.x * blockDim.x + threadIdx.x;
    if (i >= Bsz * N2O) return;
    int b = i / N2O, o = i - b * N2O;
    out[i] = (float)g_cnt2[b * N2P + idx_out[o]];
}

// ---------------- launch ----------------
extern "C" void kernel_launch(void* const* d_in, const int* in_sizes, int n_in,
                              void* d_out, int out_size) {
    const float* x    = (const float*)d_in[0];
    const float* w0   = (const float*)d_in[1];
    const float* t0   = (const float*)d_in[2];
    const float* w2   = (const float*)d_in[3];
    const float* t2   = (const float*)d_in[4];
    const int*   idx0 = (const int*)d_in[5];
    const int*   idx1 = (const int*)d_in[6];
    const int*   idx2 = (const int*)d_in[7];
    const int*   idxo = (const int*)d_in[8];
    float* out = (float*)d_out;

    void *pA0, *pW0h, *pW0l, *pD0, *pA1, *pW2h, *pW2l, *pD1, *pC0, *pC2;
    cudaGetSymbolAddress(&pA0, g_A0h);
    cudaGetSymbolAddress(&pW0h, g_W0h);
    cudaGetSymbolAddress(&pW0l, g_W0l);
    cudaGetSymbolAddress(&pD0, g_D0);
    cudaGetSymbolAddress(&pA1, g_A1h);
    cudaGetSymbolAddress(&pW2h, g_W2h);
    cudaGetSymbolAddress(&pW2l, g_W2l);
    cudaGetSymbolAddress(&pD1, g_D1);
    cudaGetSymbolAddress(&pC0, g_cnt0);
    cudaGetSymbolAddress(&pC2, g_cnt2);

    cudaFuncSetAttribute(gemm_hi, cudaFuncAttributeMaxDynamicSharedMemorySize, GSMEM);
    cudaFuncSetAttribute(gemm_lo_lif, cudaFuncAttributeMaxDynamicSharedMemorySize, GSMEM);

    k_mask0<<<(Bsz * K1 + 255) / 256, 256>>>(x);
    k_split_w0<<<(N1 * K1 / 4 + 255) / 256, 256>>>(w0);
    k_split_w2<<<(N2P * K2 + 255) / 256, 256>>>(w2);
    k_build_A0<<<(M1 * K1 / 8 + 255) / 256, 256>>>(idx0);

    dim3 g1(N1 / 128, M1 / 128);
    gemm_hi<<<g1, 256, GSMEM>>>((const __half*)pA0, (const __half*)pW0h,
                                (float*)pD0, K1, N1);
    gemm_lo_lif<<<g1, 256, GSMEM>>>((const __half*)pA0, (const __half*)pW0l,
                                    (const float*)pD0, (int*)pC0, t0, K1, N1);

    k_pool<<<(Bsz * K2 + 255) / 256, 256>>>(idx1);
    k_build_A1<<<(M1 * K2 / 8 + 255) / 256, 256>>>(idx2);

    dim3 g2(N2P / 128, M1 / 128);
    gemm_hi<<<g2, 256, GSMEM>>>((const __half*)pA1, (const __half*)pW2h,
                                (float*)pD1, K2, N2P);
    gemm_lo_lif<<<g2, 256, GSMEM>>>((const __half*)pA1, (const __half*)pW2l,
                                    (const float*)pD1, (int*)pC2, t2, K2, N2P);

    k_out<<<(Bsz * N2O + 255) / 256, 256>>>(idxo, out);
    (void)in_sizes; (void)n_in; (void)out_size;
}

// round 12
// speedup vs baseline: 3.6435x; 1.0139x over previous
#include <cuda_runtime.h>
#include <cuda_fp16.h>
#include <cstdint>

// ---------------- problem constants ----------------
#define Bsz   64
#define Tst   32
#define M1    2048        // Bsz*Tst GEMM rows
#define K1    4096
#define N1    4096
#define K2    1024
#define N2P   1024
#define N2O   1000

#define LO_SCALE    2048.0f
#define LO_INV      (1.0f / 2048.0f)

// ---------------- scratch (device globals; no allocation) ----------------
__device__ __half    g_A0h[M1 * K1];
__device__ __half    g_W0h[N1 * K1];
__device__ __half    g_W0l[N1 * K1];     // residual * 2048
__device__ float     g_D0 [M1 * N1];     // hi-pass partial for layer0
__device__ uint32_t  g_mask0[Bsz * K1];
__device__ int       g_cnt0[Bsz * N1];
__device__ uint32_t  g_mask1[Bsz * K2];
__device__ __half    g_A1h[M1 * K2];
__device__ __half    g_W2h[N2P * K2];
__device__ __half    g_W2l[N2P * K2];
__device__ float     g_D1h[M1 * N2P];
__device__ float     g_D1l[M1 * N2P];
__device__ int       g_cnt2[Bsz * N2P];

// ---------------- PTX helpers (baseline ISA only) ----------------
__device__ __forceinline__ uint32_t smem_u32(const void* p) {
    uint32_t a;
    asm("{ .reg .u64 t; cvta.to.shared.u64 t, %1; cvt.u32.u64 %0, t; }" : "=r"(a) : "l"(p));
    return a;
}
#define CP_ASYNC16(dst, src) \
    asm volatile("cp.async.cg.shared.global [%0], [%1], 16;" :: "r"(dst), "l"(src))
#define CP_COMMIT() asm volatile("cp.async.commit_group;" ::: "memory")
#define CP_WAIT2()  asm volatile("cp.async.wait_group 2;" ::: "memory")

#define LDSM4(r0, r1, r2, r3, addr) \
    asm volatile("ldmatrix.sync.aligned.m8n8.x4.shared.b16 {%0,%1,%2,%3}, [%4];" \
                 : "=r"(r0), "=r"(r1), "=r"(r2), "=r"(r3) : "r"(addr))

#define MMA16816(c, a, b) \
    asm volatile("mma.sync.aligned.m16n8k16.row.col.f32.f16.f16.f32 " \
                 "{%0,%1,%2,%3},{%4,%5,%6,%7},{%8,%9},{%0,%1,%2,%3};" \
                 : "+f"((c)[0]), "+f"((c)[1]), "+f"((c)[2]), "+f"((c)[3]) \
                 : "r"((a)[0]), "r"((a)[1]), "r"((a)[2]), "r"((a)[3]), \
                   "r"((b)[0]), "r"((b)[1]))

// ---------------- GEMM mainloop (shared) ----------------
// BM=128, BN=128, BK=32, 4-stage cp.async, 8 warps (2m x 4n), warp 64x32.
#define BKh   32
#define RS    40
#define STAGE_B (128 * RS * 2 * 2)
#define GSMEM  (4 * STAGE_B)       // 81920 B; also covers epilogue floats
#define EPITCH 132

__device__ __forceinline__ void gemm_mainloop(
    const __half* __restrict__ A, const __half* __restrict__ W,
    float cc[4][4][4], uint32_t sb, int K, int bm, int bn,
    int tid, int lane, int warp_m, int warp_n) {

    const int nkb = K / BKh;

    auto issue = [&](int kb, int stage) {
        int kk = kb * BKh;
        uint32_t sA = sb + stage * STAGE_B;
        uint32_t sB = sA + 128 * RS * 2;
#pragma unroll
        for (int i = tid; i < 1024; i += 256) {
            int isB = (i >> 9);
            int t = i & 511;
            int row = t >> 2, kc = (t & 3) * 8;
            uint32_t dst = (isB ? sB : sA) + (uint32_t)(row * RS + kc) * 2;
            const __half* src = isB ? (W + (size_t)(bn + row) * K + kk + kc)
                                    : (A + (size_t)(bm + row) * K + kk + kc);
            CP_ASYNC16(dst, src);
        }
        CP_COMMIT();
    };

    issue(0, 0); issue(1, 1); issue(2, 2);

    const int a_r = (lane & 15), a_c8 = ((lane >> 4) << 3);
    const int b_r = ((lane >> 4) << 3) + (lane & 7), b_c8 = ((lane >> 3) & 1) << 3;

    for (int kb = 0; kb < nkb; kb++) {
        CP_WAIT2();
        __syncthreads();
        if (kb + 3 < nkb) issue(kb + 3, (kb + 3) & 3);

        uint32_t sA = sb + (kb & 3) * STAGE_B;
        uint32_t sB = sA + 128 * RS * 2;
#pragma unroll
        for (int ks = 0; ks < 32; ks += 16) {
            uint32_t a[4][4], b[4][2];
#pragma unroll
            for (int mf = 0; mf < 4; mf++) {
                uint32_t ad = sA + (uint32_t)((warp_m + mf * 16 + a_r) * RS + ks + a_c8) * 2;
                LDSM4(a[mf][0], a[mf][1], a[mf][2], a[mf][3], ad);
            }
#pragma unroll
            for (int bg = 0; bg < 2; bg++) {
                uint32_t bd = sB + (uint32_t)((warp_n + bg * 16 + b_r) * RS + ks + b_c8) * 2;
                LDSM4(b[2 * bg][0], b[2 * bg][1], b[2 * bg + 1][0], b[2 * bg + 1][1], bd);
            }
#pragma unroll
            for (int mf = 0; mf < 4; mf++)
#pragma unroll
                for (int nf = 0; nf < 4; nf++)
                    MMA16816(cc[mf][nf], a[mf], b[nf]);
        }
    }
    __syncthreads();
}

// ---- layer0 pass 1: D = A @ Wh^T (store) ----
__global__ void __launch_bounds__(256, 2) gemm_hi(
    const __half* __restrict__ A, const __half* __restrict__ W,
    float* __restrict__ C, int K, int ldc) {
    extern __shared__ char smem[];
    const uint32_t sb = smem_u32(smem);
    const int tid = threadIdx.x, lane = tid & 31, wid = tid >> 5;
    const int bm = blockIdx.y * 128, bn = blockIdx.x * 128;
    const int warp_m = (wid >> 2) * 64, warp_n = (wid & 3) * 32;

    float cc[4][4][4];
#pragma unroll
    for (int i = 0; i < 4; i++)
#pragma unroll
        for (int j = 0; j < 4; j++)
#pragma unroll
            for (int q = 0; q < 4; q++) cc[i][j][q] = 0.0f;

    gemm_mainloop(A, W, cc, sb, K, bm, bn, tid, lane, warp_m, warp_n);

#pragma unroll
    for (int mf = 0; mf < 4; mf++) {
        int r0 = bm + warp_m + mf * 16 + (lane >> 2);
#pragma unroll
        for (int nf = 0; nf < 4; nf++) {
            int c0 = bn + warp_n + nf * 8 + (lane & 3) * 2;
            *reinterpret_cast<float2*>(&C[(size_t)r0 * ldc + c0]) =
                make_float2(cc[mf][nf][0], cc[mf][nf][1]);
            *reinterpret_cast<float2*>(&C[(size_t)(r0 + 8) * ldc + c0]) =
                make_float2(cc[mf][nf][2], cc[mf][nf][3]);
        }
    }
}

// ---- layer0 pass 2: D = Cin + LO_INV * (A @ Wl^T), then LIF scan -> counts ----
__global__ void __launch_bounds__(256, 2) gemm_lo_lif(
    const __half* __restrict__ A, const __half* __restrict__ W,
    const float* __restrict__ Cin, int* __restrict__ cnt,
    const float* __restrict__ thp, int K, int ldc) {
    extern __shared__ char smem[];
    const uint32_t sb = smem_u32(smem);
    const int tid = threadIdx.x, lane = tid & 31, wid = tid >> 5;
    const int bm = blockIdx.y * 128, bn = blockIdx.x * 128;
    const int warp_m = (wid >> 2) * 64, warp_n = (wid & 3) * 32;

    float cc[4][4][4];
#pragma unroll
    for (int i = 0; i < 4; i++)
#pragma unroll
        for (int j = 0; j < 4; j++)
#pragma unroll
            for (int q = 0; q < 4; q++) cc[i][j][q] = 0.0f;

    gemm_mainloop(A, W, cc, sb, K, bm, bn, tid, lane, warp_m, warp_n);

    float* ep = reinterpret_cast<float*>(smem);
#pragma unroll
    for (int mf = 0; mf < 4; mf++) {
        int rl = warp_m + mf * 16 + (lane >> 2);
        int rg = bm + rl;
#pragma unroll
        for (int nf = 0; nf < 4; nf++) {
            int cl = warp_n + nf * 8 + (lane & 3) * 2;
            int cg = bn + cl;
            float2 o0 = *reinterpret_cast<const float2*>(&Cin[(size_t)rg * ldc + cg]);
            float2 o1 = *reinterpret_cast<const float2*>(&Cin[(size_t)(rg + 8) * ldc + cg]);
            ep[rl * EPITCH + cl]           = o0.x + LO_INV * cc[mf][nf][0];
            ep[rl * EPITCH + cl + 1]       = o0.y + LO_INV * cc[mf][nf][1];
            ep[(rl + 8) * EPITCH + cl]     = o1.x + LO_INV * cc[mf][nf][2];
            ep[(rl + 8) * EPITCH + cl + 1] = o1.y + LO_INV * cc[mf][nf][3];
        }
    }
    __syncthreads();
    float th = *thp;
#pragma unroll
    for (int task = tid; task < 512; task += 256) {
        int bb = task >> 7, oo = task & 127;
        const float* col = ep + (bb * 32) * EPITCH + oo;
        float memb = 0.0f; int c = 0;
#pragma unroll
        for (int t = 0; t < Tst; t++) {
            memb += col[t * EPITCH];
            if (th < memb) { c++; memb -= th; }
        }
        cnt[((bm >> 5) + bb) * ldc + bn + oo] = c;
    }
}

// ---- layer2: hi and lo GEMMs in ONE launch (blockIdx.z selects pass) ----
__global__ void __launch_bounds__(256, 2) gemm2_both(
    const __half* __restrict__ A, const __half* __restrict__ Wh,
    const __half* __restrict__ Wl, float* __restrict__ Ch,
    float* __restrict__ Cl, int K, int ldc) {
    extern __shared__ char smem[];
    const uint32_t sb = smem_u32(smem);
    const int tid = threadIdx.x, lane = tid & 31, wid = tid >> 5;
    const int bm = blockIdx.y * 128, bn = blockIdx.x * 128;
    const int warp_m = (wid >> 2) * 64, warp_n = (wid & 3) * 32;
    const __half* W = blockIdx.z ? Wl : Wh;
    float* C = blockIdx.z ? Cl : Ch;

    float cc[4][4][4];
#pragma unroll
    for (int i = 0; i < 4; i++)
#pragma unroll
        for (int j = 0; j < 4; j++)
#pragma unroll
            for (int q = 0; q < 4; q++) cc[i][j][q] = 0.0f;

    gemm_mainloop(A, W, cc, sb, K, bm, bn, tid, lane, warp_m, warp_n);

#pragma unroll
    for (int mf = 0; mf < 4; mf++) {
        int r0 = bm + warp_m + mf * 16 + (lane >> 2);
#pragma unroll
        for (int nf = 0; nf < 4; nf++) {
            int c0 = bn + warp_n + nf * 8 + (lane & 3) * 2;
            *reinterpret_cast<float2*>(&C[(size_t)r0 * ldc + c0]) =
                make_float2(cc[mf][nf][0], cc[mf][nf][1]);
            *reinterpret_cast<float2*>(&C[(size_t)(r0 + 8) * ldc + c0]) =
                make_float2(cc[mf][nf][2], cc[mf][nf][3]);
        }
    }
}

// ---- layer2 combine + LIF scan: D = hi + LO_INV*lo (identical expression) ----
__global__ void k_lif2(const float* __restrict__ thp) {
    int i = blockIdx.x * blockDim.x + threadIdx.x;
    if (i >= Bsz * N2P) return;
    int b = i >> 10, o = i & 1023;
    float th = *thp;
    const float* ph = &g_D1h[(size_t)(b * Tst) * N2P + o];
    const float* pl = &g_D1l[(size_t)(b * Tst) * N2P + o];
    float memb = 0.0f; int c = 0;
#pragma unroll
    for (int t = 0; t < Tst; t++) {
        memb += ph[(size_t)t * N2P] + LO_INV * pl[(size_t)t * N2P];
        if (th < memb) { c++; memb -= th; }
    }
    g_cnt2[i] = c;
}

// ---------------- spike mask (bit-exact port of to_uniform_spikes) ----------
__device__ __forceinline__ uint32_t spike_mask(int N) {
    if (N <= 0)   return 0u;
    if (N >= Tst) return 0xFFFFFFFFu;
    float sp = (float)Tst / (float)N;
    uint32_t m = 0;
#pragma unroll
    for (int t = 0; t < Tst; t++)
        if (fmodf((float)t, sp) < 1.0f) m |= (1u << t);
    return m;
}

// ---------------- small kernels ----------------
__global__ void k_mask0(const float* __restrict__ x) {
    int i = blockIdx.x * blockDim.x + threadIdx.x;
    if (i < Bsz * K1) g_mask0[i] = spike_mask((int)rintf(x[i] * (float)Tst));
}

__global__ void k_split_w0(const float* __restrict__ w) {
    int i4 = blockIdx.x * blockDim.x + threadIdx.x;
    if (i4 >= (N1 * K1) / 4) return;
    float4 v = reinterpret_cast<const float4*>(w)[i4];
    __half h0 = __float2half(v.x), h1 = __float2half(v.y);
    __half h2 = __float2half(v.z), h3 = __float2half(v.w);
    __half2* ph = reinterpret_cast<__half2*>(g_W0h) + i4 * 2;
    ph[0] = __halves2half2(h0, h1); ph[1] = __halves2half2(h2, h3);
    __half2* pl = reinterpret_cast<__half2*>(g_W0l) + i4 * 2;
    pl[0] = __halves2half2(__float2half((v.x - __half2float(h0)) * LO_SCALE),
                           __float2half((v.y - __half2float(h1)) * LO_SCALE));
    pl[1] = __halves2half2(__float2half((v.z - __half2float(h2)) * LO_SCALE),
                           __float2half((v.w - __half2float(h3)) * LO_SCALE));
}

__global__ void k_split_w2(const float* __restrict__ w) {
    int i4 = blockIdx.x * blockDim.x + threadIdx.x;
    if (i4 >= (N2P * K2) / 4) return;
    int base = i4 * 4;
    int n = base >> 10;
    float4 v;
    if (n < N2O) v = *reinterpret_cast<const float4*>(w + (size_t)n * K2 + (base & 1023));
    else         v = make_float4(0.f, 0.f, 0.f, 0.f);
    __half h0 = __float2half(v.x), h1 = __float2half(v.y);
    __half h2 = __float2half(v.z), h3 = __float2half(v.w);
    __half2* ph = reinterpret_cast<__half2*>(g_W2h) + i4 * 2;
    ph[0] = __halves2half2(h0, h1); ph[1] = __halves2half2(h2, h3);
    __half2* pl = reinterpret_cast<__half2*>(g_W2l) + i4 * 2;
    pl[0] = __halves2half2(__float2half((v.x - __half2float(h0)) * LO_SCALE),
                           __float2half((v.y - __half2float(h1)) * LO_SCALE));
    pl[1] = __halves2half2(__float2half((v.z - __half2float(h2)) * LO_SCALE),
                           __float2half((v.w - __half2float(h3)) * LO_SCALE));
}

__global__ void k_build_A0(const int* __restrict__ idx0) {
    int i8 = blockIdx.x * blockDim.x + threadIdx.x;
    if (i8 >= (M1 * K1) / 8) return;
    int base = i8 * 8;
    int r = base >> 12, j0 = base & 4095;
    int b = r >> 5, t = r & 31;
    const int4* ip = reinterpret_cast<const int4*>(idx0 + j0);
    int4 iv0 = ip[0], iv1 = ip[1];
    const uint32_t* mk = g_mask0 + b * K1;
    int d[8] = {iv0.x, iv0.y, iv0.z, iv0.w, iv1.x, iv1.y, iv1.z, iv1.w};
    uint16_t h[8];
#pragma unroll
    for (int q = 0; q < 8; q++)
        h[q] = ((mk[d[q]] >> t) & 1u) ? 0x3C00 : 0x0000;
    reinterpret_cast<uint4*>(g_A0h)[i8] =
        make_uint4((uint32_t)h[0] | ((uint32_t)h[1] << 16),
                   (uint32_t)h[2] | ((uint32_t)h[3] << 16),
                   (uint32_t)h[4] | ((uint32_t)h[5] << 16),
                   (uint32_t)h[6] | ((uint32_t)h[7] << 16));
}

__global__ void k_pool(const int* __restrict__ idx1) {
    int i = blockIdx.x * blockDim.x + threadIdx.x;
    if (i >= Bsz * K2) return;
    int b = i >> 10, m = i & 1023;
    int c = m >> 4, rem = m & 15, pi = rem >> 2, pj = rem & 3;
    int sum = 0;
#pragma unroll
    for (int di = 0; di < 2; di++)
#pragma unroll
        for (int dj = 0; dj < 2; dj++) {
            int k = c * 64 + (pi * 2 + di) * 8 + (pj * 2 + dj);
            sum += g_cnt0[b * 4096 + idx1[k]];
        }
    float y = (float)sum * (1.0f / 128.0f);
    y = fminf(fmaxf(y, 0.0f), 1.0f);
    g_mask1[i] = spike_mask((int)rintf(y * (float)Tst));
}

__global__ void k_build_A1(const int* __restrict__ idx2) {
    int i8 = blockIdx.x * blockDim.x + threadIdx.x;
    if (i8 >= (M1 * K2) / 8) return;
    int base = i8 * 8;
    int r = base >> 10, j0 = base & 1023;
    int b = r >> 5, t = r & 31;
    const int4* ip = reinterpret_cast<const int4*>(idx2 + j0);
    int4 iv0 = ip[0], iv1 = ip[1];
    const uint32_t* mk = g_mask1 + b * K2;
    int d[8] = {iv0.x, iv0.y, iv0.z, iv0.w, iv1.x, iv1.y, iv1.z, iv1.w};
    uint16_t h[8];
#pragma unroll
    for (int q = 0; q < 8; q++)
        h[q] = ((mk[d[q]] >> t) & 1u) ? 0x3C00 : 0x0000;
    reinterpret_cast<uint4*>(g_A1h)[i8] =
        make_uint4((uint32_t)h[0] | ((uint32_t)h[1] << 16),
                   (uint32_t)h[2] | ((uint32_t)h[3] << 16),
                   (uint32_t)h[4] | ((uint32_t)h[5] << 16),
                   (uint32_t)h[6] | ((uint32_t)h[7] << 16));
}

__global__ void k_out(const int* __restrict__ idx_out, float* __restrict__ out) {
    int i = blockIdx.x * blockDim.x + threadIdx.x;
    if (i >= Bsz * N2O) return;
    int b = i / N2O, o = i - b * N2O;
    out[i] = (float)g_cnt2[b * N2P + idx_out[o]];
}

// ---------------- launch ----------------
extern "C" void kernel_launch(void* const* d_in, const int* in_sizes, int n_in,
                              void* d_out, int out_size) {
    const float* x    = (const float*)d_in[0];
    const float* w0   = (const float*)d_in[1];
    const float* t0   = (const float*)d_in[2];
    const float* w2   = (const float*)d_in[3];
    const float* t2   = (const float*)d_in[4];
    const int*   idx0 = (const int*)d_in[5];
    const int*   idx1 = (const int*)d_in[6];
    const int*   idx2 = (const int*)d_in[7];
    const int*   idxo = (const int*)d_in[8];
    float* out = (float*)d_out;

    void *pA0, *pW0h, *pW0l, *pD0, *pA1, *pW2h, *pW2l, *pD1h, *pD1l, *pC0;
    cudaGetSymbolAddress(&pA0, g_A0h);
    cudaGetSymbolAddress(&pW0h, g_W0h);
    cudaGetSymbolAddress(&pW0l, g_W0l);
    cudaGetSymbolAddress(&pD0, g_D0);
    cudaGetSymbolAddress(&pA1, g_A1h);
    cudaGetSymbolAddress(&pW2h, g_W2h);
    cudaGetSymbolAddress(&pW2l, g_W2l);
    cudaGetSymbolAddress(&pD1h, g_D1h);
    cudaGetSymbolAddress(&pD1l, g_D1l);
    cudaGetSymbolAddress(&pC0, g_cnt0);

    cudaFuncSetAttribute(gemm_hi, cudaFuncAttributeMaxDynamicSharedMemorySize, GSMEM);
    cudaFuncSetAttribute(gemm_lo_lif, cudaFuncAttributeMaxDynamicSharedMemorySize, GSMEM);
    cudaFuncSetAttribute(gemm2_both, cudaFuncAttributeMaxDynamicSharedMemorySize, GSMEM);

    k_mask0<<<(Bsz * K1 + 255) / 256, 256>>>(x);
    k_split_w0<<<(N1 * K1 / 4 + 255) / 256, 256>>>(w0);
    k_split_w2<<<(N2P * K2 / 4 + 255) / 256, 256>>>(w2);
    k_build_A0<<<(M1 * K1 / 8 + 255) / 256, 256>>>(idx0);

    dim3 g1(N1 / 128, M1 / 128);
    gemm_hi<<<g1, 256, GSMEM>>>((const __half*)pA0, (const __half*)pW0h,
                                (float*)pD0, K1, N1);
    gemm_lo_lif<<<g1, 256, GSMEM>>>((const __half*)pA0, (const __half*)pW0l,
                                    (const float*)pD0, (int*)pC0, t0, K1, N1);

    k_pool<<<(Bsz * K2 + 255) / 256, 256>>>(idx1);
    k_build_A1<<<(M1 * K2 / 8 + 255) / 256, 256>>>(idx2);

    dim3 g2(N2P / 128, M1 / 128, 2);   // z: 0 = hi, 1 = lo (independent GEMMs)
    gemm2_both<<<g2, 256, GSMEM>>>((const __half*)pA1, (const __half*)pW2h,
                                   (const __half*)pW2l, (float*)pD1h,
                                   (float*)pD1l, K2, N2P);
    k_lif2<<<(Bsz * N2P + 255) / 256, 256>>>(t2);

    k_out<<<(Bsz * N2O + 255) / 256, 256>>>(idxo, out);
    (void)in_sizes; (void)n_in; (void)out_size;
}